// round 2
// baseline (speedup 1.0000x reference)
#include <cuda_runtime.h>

// Problem constants (fixed by the reference)
#define B_ 32
#define H_ 3
#define M_ 2048
#define D_ 512
#define L_ 32
#define T_ 2049

#define NCHUNK 64
#define CHUNK (M_ / NCHUNK)   // 32 memories per chunk

// Scratch (allocation-free rule: __device__ globals)
__device__ float g_logits[B_ * M_];              // logits per (b,m)
__device__ float g_opart[B_ * NCHUNK * D_];      // 4 MB: per-chunk output partials

// ---------------------------------------------------------------------------
// u0[b,d] = sum_l B_emb[query[b,l], d] * pos_enc[l, d]
// ---------------------------------------------------------------------------
__global__ void u0_kernel(const int* __restrict__ query,
                          const float* __restrict__ Bemb,
                          const float* __restrict__ pos,
                          float* __restrict__ u) {
    __shared__ int sq[L_];
    int b = blockIdx.x, d = threadIdx.x;
    if (d < L_) sq[d] = query[b * L_ + d];
    __syncthreads();
    float acc = 0.f;
#pragma unroll
    for (int l = 0; l < L_; ++l) {
        acc += Bemb[(size_t)sq[l] * D_ + d] * pos[l * D_ + d];
    }
    u[b * D_ + d] = acc;
}

// ---------------------------------------------------------------------------
// logit[b,m] = dot( key_mems[b,hop,m,:] + TA[hop, rt[b,m], :], u[b,:] )
// grid: (M/8, B), block 256 (one warp per row m). Key is read-once -> __ldcs.
// ---------------------------------------------------------------------------
__global__ void logits_kernel(int hop,
                              const float* __restrict__ key,
                              const float* __restrict__ TA,
                              const int* __restrict__ rt,
                              const float* __restrict__ u) {
    __shared__ float4 su[D_ / 4];
    int b = blockIdx.y;
    int tid = threadIdx.x;
    if (tid < D_ / 4) su[tid] = ((const float4*)(u + b * D_))[tid];
    __syncthreads();

    int warp = tid >> 5, lane = tid & 31;
    int m = blockIdx.x * 8 + warp;
    int t = rt[b * M_ + m];

    const float4* krow = (const float4*)(key + ((size_t)(b * H_ + hop) * M_ + m) * D_);
    const float4* trow = (const float4*)(TA + ((size_t)hop * T_ + t) * D_);

    float acc = 0.f;
#pragma unroll
    for (int k = 0; k < 4; ++k) {
        int idx = lane + 32 * k;
        float4 kv = __ldcs(krow + idx);   // stream: read exactly once, don't pollute L2
        float4 tv = __ldg(trow + idx);    // gather table: keep cached
        float4 uv = su[idx];
        acc += (kv.x + tv.x) * uv.x + (kv.y + tv.y) * uv.y
             + (kv.z + tv.z) * uv.z + (kv.w + tv.w) * uv.w;
    }
#pragma unroll
    for (int o = 16; o; o >>= 1) acc += __shfl_down_sync(0xffffffffu, acc, o);
    if (lane == 0) g_logits[b * M_ + m] = acc;
}

// ---------------------------------------------------------------------------
// Fused softmax + weighted val reduction.
// Each block: recompute softmax stats over the full logit row (L2-resident,
// 8KB), then o_part[b,c,d] = sum_{m in chunk} (val + TC[rt]) * p[m].
// grid: (NCHUNK, B), block 128 (tid = d4 lane covering all of D).
// ---------------------------------------------------------------------------
__global__ void outpart_kernel(int hop,
                               const float* __restrict__ val,
                               const float* __restrict__ TC,
                               const int* __restrict__ rt) {
    int b = blockIdx.y, c = blockIdx.x;
    int tid = threadIdx.x;

    __shared__ float red[128];
    const float* lg = g_logits + b * M_;

    // block-wide softmax stats over all M logits (16 per thread)
    float lv[M_ / 128];
    float lmax = -1e30f;
#pragma unroll
    for (int k = 0; k < M_ / 128; ++k) {
        lv[k] = lg[tid + 128 * k];
        lmax = fmaxf(lmax, lv[k]);
    }
    red[tid] = lmax;
    __syncthreads();
#pragma unroll
    for (int s = 64; s; s >>= 1) {
        if (tid < s) red[tid] = fmaxf(red[tid], red[tid + s]);
        __syncthreads();
    }
    lmax = red[0];
    __syncthreads();
    float sum = 0.f;
#pragma unroll
    for (int k = 0; k < M_ / 128; ++k) sum += __expf(lv[k] - lmax);
    red[tid] = sum;
    __syncthreads();
#pragma unroll
    for (int s = 64; s; s >>= 1) {
        if (tid < s) red[tid] += red[tid + s];
        __syncthreads();
    }
    float inv = 1.f / red[0];

    // p and rt for this block's chunk
    __shared__ float sp[CHUNK];
    __shared__ int   st[CHUNK];
    __syncthreads();
    if (tid < CHUNK) {
        sp[tid] = __expf(lg[c * CHUNK + tid] - lmax) * inv;
        st[tid] = rt[b * M_ + c * CHUNK + tid];
    }
    __syncthreads();

    const float4* vbase  = (const float4*)(val + ((size_t)(b * H_ + hop) * M_ + c * CHUNK) * D_);
    const float4* tcbase = (const float4*)(TC + (size_t)hop * T_ * D_);

    float4 acc = make_float4(0.f, 0.f, 0.f, 0.f);
#pragma unroll 4
    for (int mm = 0; mm < CHUNK; ++mm) {
        float pm = sp[mm];
        float4 vv = __ldcs(vbase + (size_t)mm * (D_ / 4) + tid);   // stream
        float4 tv = __ldg(tcbase + (size_t)st[mm] * (D_ / 4) + tid); // cached gather
        acc.x += (vv.x + tv.x) * pm;
        acc.y += (vv.y + tv.y) * pm;
        acc.z += (vv.z + tv.z) * pm;
        acc.w += (vv.w + tv.w) * pm;
    }
    ((float4*)(g_opart + ((size_t)b * NCHUNK + c) * D_))[tid] = acc;
}

// ---------------------------------------------------------------------------
// u[b,d] += sum_c o_part[b,c,d].  grid: B, block D
// ---------------------------------------------------------------------------
__global__ void update_kernel(float* __restrict__ u) {
    int b = blockIdx.x, d = threadIdx.x;
    float acc = u[b * D_ + d];
#pragma unroll
    for (int c = 0; c < NCHUNK; ++c) acc += g_opart[(size_t)(b * NCHUNK + c) * D_ + d];
    u[b * D_ + d] = acc;
}

// ---------------------------------------------------------------------------
extern "C" void kernel_launch(void* const* d_in, const int* in_sizes, int n_in,
                              void* d_out, int out_size) {
    const int*   query = (const int*)d_in[0];
    const int*   rt    = (const int*)d_in[1];
    const float* key   = (const float*)d_in[2];
    const float* val   = (const float*)d_in[3];
    const float* Bemb  = (const float*)d_in[4];
    const float* TA    = (const float*)d_in[5];
    const float* TC    = (const float*)d_in[6];
    const float* pos   = (const float*)d_in[7];
    float* u = (float*)d_out;   // [B, D]

    u0_kernel<<<B_, D_>>>(query, Bemb, pos, u);
    for (int hop = 0; hop < H_; ++hop) {
        logits_kernel<<<dim3(M_ / 8, B_), 256>>>(hop, key, TA, rt, u);
        outpart_kernel<<<dim3(NCHUNK, B_), 128>>>(hop, val, TC, rt);
        update_kernel<<<B_, D_>>>(u);
    }
}

// round 4
// speedup vs baseline: 1.2125x; 1.2125x over previous
#include <cuda_runtime.h>

// Problem constants (fixed by the reference)
#define B_ 32
#define H_ 3
#define M_ 2048
#define D_ 512
#define L_ 32
#define T_ 2049

#define NCHUNK 32
#define CHUNK (M_ / NCHUNK)   // 64 memories per chunk

// Scratch (allocation-free rule: __device__ globals)
__device__ float g_logits[B_ * M_];              // logits -> softmax p in place
__device__ float g_opart[B_ * NCHUNK * D_];      // 2 MB: per-chunk output partials

// ---------------------------------------------------------------------------
// u0[b,d] = sum_l B_emb[query[b,l], d] * pos_enc[l, d]
// ---------------------------------------------------------------------------
__global__ void u0_kernel(const int* __restrict__ query,
                          const float* __restrict__ Bemb,
                          const float* __restrict__ pos,
                          float* __restrict__ u) {
    __shared__ int sq[L_];
    int b = blockIdx.x, d = threadIdx.x;
    if (d < L_) sq[d] = query[b * L_ + d];
    __syncthreads();
    float acc = 0.f;
#pragma unroll
    for (int l = 0; l < L_; ++l) {
        acc += Bemb[(size_t)sq[l] * D_ + d] * pos[l * D_ + d];
    }
    u[b * D_ + d] = acc;
}

// ---------------------------------------------------------------------------
// logit[b,m] = dot( key_mems[b,hop,m,:] + TA[hop, rt[b,m], :], u[b,:] )
// grid: (M/8, B), block 256 (one warp per row m).
// ---------------------------------------------------------------------------
__global__ void logits_kernel(int hop,
                              const float* __restrict__ key,
                              const float* __restrict__ TA,
                              const int* __restrict__ rt,
                              const float* __restrict__ u) {
    __shared__ float4 su[D_ / 4];
    int b = blockIdx.y;
    int tid = threadIdx.x;
    if (tid < D_ / 4) su[tid] = ((const float4*)(u + b * D_))[tid];
    __syncthreads();

    int warp = tid >> 5, lane = tid & 31;
    int m = blockIdx.x * 8 + warp;
    int t = rt[b * M_ + m];

    const float4* krow = (const float4*)(key + ((size_t)(b * H_ + hop) * M_ + m) * D_);
    const float4* trow = (const float4*)(TA + ((size_t)hop * T_ + t) * D_);

    float acc = 0.f;
#pragma unroll
    for (int k = 0; k < 4; ++k) {
        int idx = lane + 32 * k;
        float4 kv = __ldcs(krow + idx);   // stream: read exactly once
        float4 tv = __ldg(trow + idx);    // gather table: L2-resident
        float4 uv = su[idx];
        acc += (kv.x + tv.x) * uv.x + (kv.y + tv.y) * uv.y
             + (kv.z + tv.z) * uv.z + (kv.w + tv.w) * uv.w;
    }
#pragma unroll
    for (int o = 16; o; o >>= 1) acc += __shfl_down_sync(0xffffffffu, acc, o);
    if (lane == 0) g_logits[b * M_ + m] = acc;
}

// ---------------------------------------------------------------------------
// softmax over M per batch, in place in g_logits. grid: B, block 256
// ---------------------------------------------------------------------------
__global__ void softmax_kernel() {
    int b = blockIdx.x, tid = threadIdx.x;
    __shared__ float red[256];
    float* lg = g_logits + b * M_;

    float v[M_ / 256];
    float lmax = -1e30f;
#pragma unroll
    for (int k = 0; k < M_ / 256; ++k) {
        v[k] = lg[tid + 256 * k];
        lmax = fmaxf(lmax, v[k]);
    }
    red[tid] = lmax;
    __syncthreads();
#pragma unroll
    for (int s = 128; s; s >>= 1) {
        if (tid < s) red[tid] = fmaxf(red[tid], red[tid + s]);
        __syncthreads();
    }
    lmax = red[0];
    __syncthreads();

    float sum = 0.f;
#pragma unroll
    for (int k = 0; k < M_ / 256; ++k) {
        v[k] = __expf(v[k] - lmax);
        sum += v[k];
    }
    red[tid] = sum;
    __syncthreads();
#pragma unroll
    for (int s = 128; s; s >>= 1) {
        if (tid < s) red[tid] += red[tid + s];
        __syncthreads();
    }
    float inv = 1.f / red[0];
#pragma unroll
    for (int k = 0; k < M_ / 256; ++k) lg[tid + 256 * k] = v[k] * inv;
}

// ---------------------------------------------------------------------------
// o_part[b,c,d] = sum_{m in chunk c} (val_mems[b,hop,m,d] + TC[hop,rt[b,m],d]) * p[b,m]
// grid: (NCHUNK, B), block 256: d4 = tid&127 float4 lane, grp = tid>>7,
// two m's in flight per d4 lane.
// ---------------------------------------------------------------------------
__global__ void outpart_kernel(int hop,
                               const float* __restrict__ val,
                               const float* __restrict__ TC,
                               const int* __restrict__ rt) {
    int b = blockIdx.y, c = blockIdx.x;
    int tid = threadIdx.x;
    int d4 = tid & 127, grp = tid >> 7;

    __shared__ float sp[CHUNK];
    __shared__ int   st[CHUNK];
    __shared__ float4 sacc[D_ / 4];

    if (tid < CHUNK) {
        sp[tid] = g_logits[b * M_ + c * CHUNK + tid];
        st[tid] = rt[b * M_ + c * CHUNK + tid];
    }
    __syncthreads();

    const float4* vbase  = (const float4*)(val + ((size_t)(b * H_ + hop) * M_ + c * CHUNK) * D_);
    const float4* tcbase = (const float4*)(TC + (size_t)hop * T_ * D_);

    float4 acc = make_float4(0.f, 0.f, 0.f, 0.f);
#pragma unroll 4
    for (int mm = grp; mm < CHUNK; mm += 2) {
        float pm = sp[mm];
        float4 vv = __ldcs(vbase + (size_t)mm * (D_ / 4) + d4);     // stream
        float4 tv = __ldg(tcbase + (size_t)st[mm] * (D_ / 4) + d4); // cached gather
        acc.x += (vv.x + tv.x) * pm;
        acc.y += (vv.y + tv.y) * pm;
        acc.z += (vv.z + tv.z) * pm;
        acc.w += (vv.w + tv.w) * pm;
    }

    if (grp == 1) sacc[d4] = acc;
    __syncthreads();
    if (grp == 0) {
        float4 o = sacc[d4];
        acc.x += o.x; acc.y += o.y; acc.z += o.z; acc.w += o.w;
        ((float4*)(g_opart + ((size_t)b * NCHUNK + c) * D_))[d4] = acc;
    }
}

// ---------------------------------------------------------------------------
// u[b,d] += sum_c o_part[b,c,d].  grid: (B,4), block 128
// ---------------------------------------------------------------------------
__global__ void update_kernel(float* __restrict__ u) {
    int b = blockIdx.x;
    int d = blockIdx.y * 128 + threadIdx.x;
    float acc = u[b * D_ + d];
#pragma unroll
    for (int c = 0; c < NCHUNK; ++c) acc += g_opart[(size_t)(b * NCHUNK + c) * D_ + d];
    u[b * D_ + d] = acc;
}

// ---------------------------------------------------------------------------
extern "C" void kernel_launch(void* const* d_in, const int* in_sizes, int n_in,
                              void* d_out, int out_size) {
    const int*   query = (const int*)d_in[0];
    const int*   rt    = (const int*)d_in[1];
    const float* key   = (const float*)d_in[2];
    const float* val   = (const float*)d_in[3];
    const float* Bemb  = (const float*)d_in[4];
    const float* TA    = (const float*)d_in[5];
    const float* TC    = (const float*)d_in[6];
    const float* pos   = (const float*)d_in[7];
    float* u = (float*)d_out;   // [B, D]

    u0_kernel<<<B_, D_>>>(query, Bemb, pos, u);
    for (int hop = 0; hop < H_; ++hop) {
        logits_kernel<<<dim3(M_ / 8, B_), 256>>>(hop, key, TA, rt, u);
        softmax_kernel<<<B_, 256>>>();
        outpart_kernel<<<dim3(NCHUNK, B_), 256>>>(hop, val, TC, rt);
        update_kernel<<<dim3(B_, 4), 128>>>(u);
    }
}